// round 5
// baseline (speedup 1.0000x reference)
#include <cuda_runtime.h>
#include <cuda_bf16.h>
#include <cstdint>

#define BB    2048
#define CC    9605
#define LL    8
#define NT    256
#define TOPK  16
#define TVAL  2.0f
#define CAP   1024
#define NW    (NT / 32)

#define ALPHA   0.5f
#define ALPHA1  0.05f
#define ALPHA2  2.0f
#define ALPHA3  5.0f
#define ALPHA_OTHER 0.3f

// Scratch (no cudaMalloc allowed)
__device__ float         g_partial[BB];
__device__ unsigned char g_gbits[CC + 16];
__device__ unsigned int  g_gw[4][CC / 4 + 4];   // packed gbit words, one view per peel phase
__device__ int           g_done;                // zero-init; reset by last block each call

__device__ __forceinline__ float sigm(float v) { return 1.0f / (1.0f + __expf(-v)); }

__device__ __forceinline__ float rankl(float x1, float x2) {
    float d = x2 - x1 + ALPHA1;
    float s = 1.0f / (1.0f + __expf(-ALPHA3 * d));
    return d > 0.0f ? ALPHA2 * s : s;
}

// ---------------------------------------------------------------------------
// prep1: classify mask dtype from byte pattern (every block, redundantly),
// then build per-class group-membership bytes.
//   f32 1.0 -> bytes {00,00,80,3F}: some byte has a bit above bit0 -> word mode
//   i32 1   -> ones only at offset%4==0                            -> word mode
//   bool    -> 0x01 at arbitrary byte offsets                      -> byte mode
// ---------------------------------------------------------------------------
__global__ void prep1_kernel(const unsigned char* __restrict__ mraw) {
    __shared__ int s_gt1, s_mis;
    if (threadIdx.x == 0) { s_gt1 = 0; s_mis = 0; }
    __syncthreads();
    const unsigned int* mw = (const unsigned int*)mraw;
    unsigned int a = 0, bm = 0;
    for (int i = threadIdx.x; i < (CC * LL) / 4; i += blockDim.x) {   // 19210 words exact
        unsigned int wv = mw[i];
        a  |= (wv & 0xFEFEFEFEu);   // any byte >= 2 anywhere
        bm |= (wv & 0x01010100u);   // bit0 set in bytes at offset%4 != 0
    }
    if (a)  atomicOr(&s_gt1, 1);
    if (bm) atomicOr(&s_mis, 1);
    __syncthreads();
    const int bytemode = (!s_gt1) && s_mis;

    int c = blockIdx.x * blockDim.x + threadIdx.x;
    if (c < CC) {
        unsigned int bits = 0;
        if (bytemode) {
            #pragma unroll
            for (int l = 0; l < LL; ++l)
                if (mraw[l * CC + c] != 0) bits |= (1u << l);
        } else {
            #pragma unroll
            for (int l = 0; l < LL; ++l)
                if (mw[l * CC + c] != 0u) bits |= (1u << l);
        }
        g_gbits[c] = (unsigned char)bits;
    }
}

// ---------------------------------------------------------------------------
// prep2: pack gbits into u32 words for each of the 4 peel phases.
// View a covers float4 index v -> classes p+4v .. p+4v+3, p = (4-a)&3.
// ---------------------------------------------------------------------------
__global__ void prep2_kernel() {
    int idx = blockIdx.x * blockDim.x + threadIdx.x;
    int a = idx / (CC / 4 + 1);
    int j = idx % (CC / 4 + 1);
    if (a >= 4) return;
    int p = (4 - a) & 3;
    int nva = (CC - p) >> 2;
    if (j >= nva) return;
    int c = p + 4 * j;
    unsigned int wv = (unsigned int)g_gbits[c]
                    | ((unsigned int)g_gbits[c + 1] << 8)
                    | ((unsigned int)g_gbits[c + 2] << 16)
                    | ((unsigned int)g_gbits[c + 3] << 24);
    g_gw[a][j] = wv;
}

// ---------------------------------------------------------------------------
// row_kernel: one CTA per sample. Single fused streaming pass:
//   group maxes / hit bitmasks / threshold-gated candidate compaction.
// Exact top-16 from candidates when >=16 exceed TVAL (guaranteed fallback
// re-scan otherwise). Last CTA reduces partials deterministically.
// ---------------------------------------------------------------------------
__global__ __launch_bounds__(NT) void row_kernel(const float* __restrict__ x,
                                                 const float* __restrict__ y,
                                                 const float* __restrict__ yn,
                                                 float* __restrict__ out) {
    __shared__ float s_cand[CAP];
    __shared__ float s_top[NT * TOPK];          // merge workspace / final reduce buf
    __shared__ float s_gmax[NW][LL];
    __shared__ float s_umax[NW];
    __shared__ unsigned int s_gtb[NW], s_gnb[NW];
    __shared__ int s_ncand, s_cnt, s_last;

    const int b = blockIdx.x, t = threadIdx.x, w = t >> 5;
    const size_t base = (size_t)b * CC;
    const float* __restrict__ xr = x + base;
    const float* __restrict__ yr = y + base;
    const float* __restrict__ nr = yn + base;

    if (t == 0) { s_ncand = 0; s_cnt = 0; }
    __syncthreads();

    const float NI = __int_as_float(0xff800000);
    float gmax[LL];
    #pragma unroll
    for (int l = 0; l < LL; ++l) gmax[l] = NI;
    float umax = NI;
    unsigned int gtb = 0, gnb = 0;
    int cnt = 0;

    // alignment: (b*9605) % 4 == b % 4  (9605 % 4 == 1)
    const int a  = b & 3;
    const int p  = (4 - a) & 3;              // scalar peel count
    const int nv = (CC - p) >> 2;            // float4 count
    const int r  = (CC - p) & 3;             // scalar tail count
    const unsigned int* __restrict__ gw = g_gw[a];

    // ---- scalar peel + tail (<= 5 elements) ----
    if (t < p + r) {
        int idx = (t < p) ? t : (p + 4 * nv + (t - p));
        float xv = __ldg(xr + idx);
        if (xv > TVAL) {
            ++cnt;
            int pos = atomicAdd(&s_ncand, 1);
            if (pos < CAP) s_cand[pos] = xv;
        }
        unsigned int gb = g_gbits[idx];
        if (gb) {
            umax = fmaxf(umax, xv);
            #pragma unroll
            for (int l = 0; l < LL; ++l)
                if (gb & (1u << l)) gmax[l] = fmaxf(gmax[l], xv);
            if (__ldg(yr + idx) > 0.0f) gtb |= gb;
            if (__ldg(nr + idx) > 0.0f) gnb |= gb;
        }
    }

    // ---- vectorized main pass ----
    const float4* __restrict__ x4 = (const float4*)(xr + p);
    const float4* __restrict__ y4 = (const float4*)(yr + p);
    const float4* __restrict__ n4 = (const float4*)(nr + p);

    for (int v = t; v < nv; v += NT) {
        float4 xv = __ldcs(x4 + v);               // read once, evict-first
        unsigned int gwv = __ldg(gw + v);         // L1/L2-resident metadata

        // threshold-gated candidate compaction (rare: ~2.3% of elements)
        #define CAND(XV)                                          \
            if ((XV) > TVAL) {                                    \
                ++cnt;                                            \
                int _pos = atomicAdd(&s_ncand, 1);                \
                if (_pos < CAP) s_cand[_pos] = (XV);              \
            }
        CAND(xv.x) CAND(xv.y) CAND(xv.z) CAND(xv.w)
        #undef CAND

        if (gwv) {                                // y/yn only needed on grouped classes
            float4 yv  = __ldcs(y4 + v);
            float4 nvv = __ldcs(n4 + v);
            unsigned int g0 = gwv & 0xffu, g1 = (gwv >> 8) & 0xffu,
                         g2 = (gwv >> 16) & 0xffu, g3 = gwv >> 24;
            #define P1(GB, XV, YV, NV)                                              \
                if (GB) {                                                            \
                    umax = fmaxf(umax, XV);                                          \
                    _Pragma("unroll")                                                \
                    for (int l = 0; l < LL; ++l)                                     \
                        if ((GB) & (1u << l)) gmax[l] = fmaxf(gmax[l], XV);          \
                    if ((YV) > 0.0f) gtb |= (GB);                                    \
                    if ((NV) > 0.0f) gnb |= (GB);                                    \
                }
            P1(g0, xv.x, yv.x, nvv.x)
            P1(g1, xv.y, yv.y, nvv.y)
            P1(g2, xv.z, yv.z, nvv.z)
            P1(g3, xv.w, yv.w, nvv.w)
            #undef P1
        }
    }

    // ---- warp-reduce aggregates ----
    const unsigned fm = 0xFFFFFFFFu;
    #pragma unroll
    for (int off = 16; off > 0; off >>= 1) {
        #pragma unroll
        for (int l = 0; l < LL; ++l)
            gmax[l] = fmaxf(gmax[l], __shfl_xor_sync(fm, gmax[l], off));
        umax = fmaxf(umax, __shfl_xor_sync(fm, umax, off));
        gtb |= __shfl_xor_sync(fm, gtb, off);
        gnb |= __shfl_xor_sync(fm, gnb, off);
        cnt += __shfl_xor_sync(fm, cnt, off);
    }
    if ((t & 31) == 0) {
        #pragma unroll
        for (int l = 0; l < LL; ++l) s_gmax[w][l] = gmax[l];
        s_umax[w] = umax;
        s_gtb[w] = gtb;
        s_gnb[w] = gnb;
        atomicAdd(&s_cnt, cnt);
    }
    __syncthreads();

    const int total = s_cnt;

    // ---- top-16 selection ----
    float tk[TOPK];
    #pragma unroll
    for (int k = 0; k < TOPK; ++k) tk[k] = NI;

    #define INS(XV)                                                            \
        if ((XV) > tk[TOPK - 1]) {                                             \
            float _v = (XV);                                                   \
            _Pragma("unroll")                                                  \
            for (int k = 0; k < TOPK; ++k)                                     \
                if (_v > tk[k]) { float _tmp = tk[k]; tk[k] = _v; _v = _tmp; } \
        }

    if (total >= TOPK && total <= CAP) {
        // fast path: exact — top-16 must all exceed TVAL, all such are in s_cand
        for (int i = t; i < total; i += NT) {
            float xv = s_cand[i];
            INS(xv)
        }
    } else {
        // rare exact fallback: full re-scan with unconditional insertion
        for (int i = t; i < CC; i += NT) {
            float xv = __ldg(xr + i);
            INS(xv)
        }
    }
    #undef INS

    #pragma unroll
    for (int k = 0; k < TOPK; ++k) s_top[t * TOPK + k] = tk[k];
    __syncthreads();

    // merge tree over NT top-16 lists
    for (int s = NT / 2; s >= 1; s >>= 1) {
        if (t < s) {
            float o[TOPK];
            const float* A  = &s_top[t * TOPK];
            const float* Bp = &s_top[(t + s) * TOPK];
            int i = 0, j = 0;
            #pragma unroll
            for (int k = 0; k < TOPK; ++k) {
                float av = A[i], cv = Bp[j];
                if (av >= cv) { o[k] = av; ++i; } else { o[k] = cv; ++j; }
            }
            float* Aw = &s_top[t * TOPK];
            #pragma unroll
            for (int k = 0; k < TOPK; ++k) Aw[k] = o[k];
        }
        __syncthreads();
    }

    // ---- per-row loss (thread 0) ----
    if (t == 0) {
        float gmaxA[LL];
        #pragma unroll
        for (int l = 0; l < LL; ++l) gmaxA[l] = NI;
        float umaxA = NI;
        unsigned int gtA = 0, gnA = 0;
        for (int wv = 0; wv < NW; ++wv) {
            #pragma unroll
            for (int l = 0; l < LL; ++l) gmaxA[l] = fmaxf(gmaxA[l], s_gmax[wv][l]);
            umaxA = fmaxf(umaxA, s_umax[wv]);
            gtA |= s_gtb[wv];
            gnA |= s_gnb[wv];
        }

        float t16   = s_top[TOPK - 1];               // exact 16th-largest raw x
        float thres = fmaxf(sigm(t16), ALPHA_OTHER);

        float loss;
        if (gtA) {
            loss = 0.0f;
            #pragma unroll
            for (int l = 0; l < LL; ++l) {
                float gm = sigm(gmaxA[l]);
                loss += ((gtA >> l) & 1u) ? rankl(gm, thres)
                                          : rankl(thres, gm);
            }
        } else {
            float um = sigm(umaxA);
            float negs = 0.0f;                       // torch starts at 0
            if (gnA) {
                float nm = NI;
                #pragma unroll
                for (int l = 0; l < LL; ++l)
                    if ((gnA >> l) & 1u) nm = fmaxf(nm, gmaxA[l]);
                negs = sigm(nm);
            }
            loss = (1.0f - ALPHA) * rankl(thres, um) + ALPHA * rankl(thres, negs);
        }
        g_partial[b] = loss;
    }

    // ---- fused deterministic mean: last CTA reduces all partials ----
    if (t == 0) {
        __threadfence();
        int old = atomicAdd(&g_done, 1);
        s_last = (old == BB - 1);
    }
    __syncthreads();
    if (s_last) {
        float acc = 0.0f;
        for (int i = t; i < BB; i += NT) acc += g_partial[i];   // fixed order
        s_top[t] = acc;
        __syncthreads();
        for (int st = NT / 2; st > 0; st >>= 1) {
            if (t < st) s_top[t] += s_top[t + st];
            __syncthreads();
        }
        if (t == 0) { out[0] = s_top[0] / (float)BB; g_done = 0; }
    }
}

extern "C" void kernel_launch(void* const* d_in, const int* in_sizes, int n_in,
                              void* d_out, int out_size) {
    (void)in_sizes; (void)n_in; (void)out_size;
    const float*         x  = (const float*)d_in[0];
    const float*         y  = (const float*)d_in[1];
    const float*         yn = (const float*)d_in[2];
    const unsigned char* m  = (const unsigned char*)d_in[3];

    prep1_kernel<<<(CC + 1023) / 1024, 1024>>>(m);
    prep2_kernel<<<(4 * (CC / 4 + 1) + 255) / 256, 256>>>();
    row_kernel<<<BB, NT>>>(x, y, yn, (float*)d_out);
}

// round 8
// speedup vs baseline: 1.1657x; 1.1657x over previous
#include <cuda_runtime.h>
#include <cuda_bf16.h>
#include <cstdint>

#define BB    2048
#define CC    9605
#define LL    8
#define NT    256
#define TOPK  16
#define TVAL  2.0f
#define CAP   1024
#define NW    (NT / 32)
#define NVMAX (CC / 4 + 2)

#define ALPHA   0.5f
#define ALPHA1  0.05f
#define ALPHA2  2.0f
#define ALPHA3  5.0f
#define ALPHA_OTHER 0.3f

// Scratch (no cudaMalloc allowed)
__device__ float         g_partial[BB];
__device__ unsigned char g_gbits[CC + 16];
__device__ unsigned int  g_gw[4][NVMAX];   // packed gbit words, one view per peel phase
__device__ int           g_done;           // zero-init; reset by last block each call

__device__ __forceinline__ float sigm(float v) { return 1.0f / (1.0f + __expf(-v)); }

__device__ __forceinline__ float rankl(float x1, float x2) {
    float d = x2 - x1 + ALPHA1;
    float s = 1.0f / (1.0f + __expf(-ALPHA3 * d));
    return d > 0.0f ? ALPHA2 * s : s;
}

// ---------------------------------------------------------------------------
// prep: ONE block. Phase A: classify mask dtype from byte pattern.
//   f32 1.0 -> bytes {00,00,80,3F}: some byte has a bit above bit0 -> word mode
//   i32 1   -> ones only at offset%4==0                            -> word mode
//   bool    -> 0x01 at arbitrary byte offsets                      -> byte mode
// Phase B: per-class membership byte. Phase C: packed u32 views per peel phase.
// ---------------------------------------------------------------------------
__global__ __launch_bounds__(1024) void prep_kernel(const unsigned char* __restrict__ mraw) {
    __shared__ int s_gt1, s_mis;
    const int t = threadIdx.x;
    if (t == 0) { s_gt1 = 0; s_mis = 0; }
    __syncthreads();
    const unsigned int* mw = (const unsigned int*)mraw;
    unsigned int a = 0, bm = 0;
    for (int i = t; i < (CC * LL) / 4; i += 1024) {   // 19210 words exact
        unsigned int wv = mw[i];
        a  |= (wv & 0xFEFEFEFEu);   // any byte >= 2 anywhere
        bm |= (wv & 0x01010100u);   // bit0 set in bytes at offset%4 != 0
    }
    if (a)  atomicOr(&s_gt1, 1);
    if (bm) atomicOr(&s_mis, 1);
    __syncthreads();
    const int bytemode = (!s_gt1) && s_mis;

    for (int c = t; c < CC; c += 1024) {
        unsigned int bits = 0;
        if (bytemode) {
            #pragma unroll
            for (int l = 0; l < LL; ++l)
                if (mraw[l * CC + c] != 0) bits |= (1u << l);
        } else {
            #pragma unroll
            for (int l = 0; l < LL; ++l)
                if (mw[l * CC + c] != 0u) bits |= (1u << l);
        }
        g_gbits[c] = (unsigned char)bits;
    }
    __syncthreads();

    #pragma unroll
    for (int av = 0; av < 4; ++av) {
        int p = (4 - av) & 3;
        int nva = (CC - p) >> 2;
        for (int j = t; j < nva; j += 1024) {
            int c = p + 4 * j;
            g_gw[av][j] = (unsigned int)g_gbits[c]
                        | ((unsigned int)g_gbits[c + 1] << 8)
                        | ((unsigned int)g_gbits[c + 2] << 16)
                        | ((unsigned int)g_gbits[c + 3] << 24);
        }
    }
}

// ---------------------------------------------------------------------------
// row_kernel: one CTA per sample. Single fused streaming pass:
//   group maxes / hit bitmasks / warp-aggregated candidate compaction (x>TVAL).
// Streaming loop uses a UNIFORM trip count: every thread executes every
// __ballot_sync (bounds folded into the predicate) — no intra-warp exit skew.
// Exact top-16 from candidates when 16 <= count <= CAP; else exact fallback
// re-scan. Last CTA reduces the 2048 partials deterministically.
// ---------------------------------------------------------------------------
__global__ __launch_bounds__(NT) void row_kernel(const float* __restrict__ x,
                                                 const float* __restrict__ y,
                                                 const float* __restrict__ yn,
                                                 float* __restrict__ out) {
    __shared__ unsigned int s_gw[NVMAX];        // packed membership words (~9.6 KB)
    __shared__ float s_cand[CAP];
    __shared__ float s_top[NT * TOPK];          // merge workspace / final reduce buf
    __shared__ float s_gmax[NW][LL];
    __shared__ float s_umax[NW];
    __shared__ unsigned int s_gtb[NW], s_gnb[NW];
    __shared__ int s_ncand, s_last;

    const int b = blockIdx.x, t = threadIdx.x, w = t >> 5, lane = t & 31;
    const size_t base = (size_t)b * CC;
    const float* __restrict__ xr = x + base;
    const float* __restrict__ yr = y + base;
    const float* __restrict__ nr = yn + base;

    // alignment: (b*9605) % 4 == b % 4  (9605 % 4 == 1)
    const int av = b & 3;
    const int p  = (4 - av) & 3;             // scalar peel count
    const int nv = (CC - p) >> 2;            // float4 count
    const int r  = (CC - p) & 3;             // scalar tail count

    for (int i = t; i < nv; i += NT) s_gw[i] = g_gw[av][i];
    if (t == 0) s_ncand = 0;
    __syncthreads();

    const float NI = __int_as_float(0xff800000);
    float gmax[LL];
    #pragma unroll
    for (int l = 0; l < LL; ++l) gmax[l] = NI;
    float umax = NI;
    unsigned int gtb = 0, gnb = 0;
    const unsigned fm = 0xFFFFFFFFu;

    // ---- scalar peel + tail (<= 5 elements; all threads reach the ballot) ----
    {
        int active = (t < p + r);
        int idx = 0;
        float xv = NI;
        if (active) {
            idx = (t < p) ? t : (p + 4 * nv + (t - p));
            xv = __ldg(xr + idx);
        }
        unsigned int mk = __ballot_sync(fm, active && xv > TVAL);
        if (mk && w == 0) {                      // peel elements live in warp 0 only
            int bpos = 0;
            if (lane == 0) bpos = atomicAdd(&s_ncand, __popc(mk));
            bpos = __shfl_sync(fm, bpos, 0);
            if (active && xv > TVAL) {
                int my = bpos + __popc(mk & ((1u << lane) - 1u));
                if (my < CAP) s_cand[my] = xv;
            }
        }
        if (active) {
            unsigned int gb = g_gbits[idx];
            if (gb) {
                umax = fmaxf(umax, xv);
                #pragma unroll
                for (int l = 0; l < LL; ++l)
                    if (gb & (1u << l)) gmax[l] = fmaxf(gmax[l], xv);
                if (__ldg(yr + idx) > 0.0f) gtb |= gb;
                if (__ldg(nr + idx) > 0.0f) gnb |= gb;
            }
        }
    }

    // ---- vectorized main pass (uniform trip count for warp-sync safety) ----
    const float4* __restrict__ x4 = (const float4*)(xr + p);
    const float4* __restrict__ y4 = (const float4*)(yr + p);
    const float4* __restrict__ n4 = (const float4*)(nr + p);

    for (int v0 = 0; v0 < nv; v0 += NT) {
        const int v = v0 + t;
        const bool in = (v < nv);
        float4 xv;
        unsigned int gwv = 0;
        if (in) {
            xv = __ldg(x4 + v);
            gwv = s_gw[v];
        } else {
            xv.x = NI; xv.y = NI; xv.z = NI; xv.w = NI;
        }

        // warp-aggregated candidate compaction; every lane executes the ballots
        unsigned int m0 = __ballot_sync(fm, xv.x > TVAL);
        unsigned int m1 = __ballot_sync(fm, xv.y > TVAL);
        unsigned int m2 = __ballot_sync(fm, xv.z > TVAL);
        unsigned int m3 = __ballot_sync(fm, xv.w > TVAL);
        if (m0 | m1 | m2 | m3) {                 // warp-uniform branch
            int n = __popc(m0) + __popc(m1) + __popc(m2) + __popc(m3);
            int bpos = 0;
            if (lane == 0) bpos = atomicAdd(&s_ncand, n);
            bpos = __shfl_sync(fm, bpos, 0);
            unsigned int lt = (1u << lane) - 1u;
            int o = bpos;
            if (xv.x > TVAL) { int my = o + __popc(m0 & lt); if (my < CAP) s_cand[my] = xv.x; }
            o += __popc(m0);
            if (xv.y > TVAL) { int my = o + __popc(m1 & lt); if (my < CAP) s_cand[my] = xv.y; }
            o += __popc(m1);
            if (xv.z > TVAL) { int my = o + __popc(m2 & lt); if (my < CAP) s_cand[my] = xv.z; }
            o += __popc(m2);
            if (xv.w > TVAL) { int my = o + __popc(m3 & lt); if (my < CAP) s_cand[my] = xv.w; }
        }

        if (gwv) {                                // y/yn only needed on grouped classes
            float4 yv  = __ldcs(y4 + v);
            float4 nvv = __ldcs(n4 + v);
            unsigned int g0 = gwv & 0xffu, g1 = (gwv >> 8) & 0xffu,
                         g2 = (gwv >> 16) & 0xffu, g3 = gwv >> 24;
            #define P1(GB, XV, YV, NV)                                              \
                if (GB) {                                                            \
                    umax = fmaxf(umax, XV);                                          \
                    _Pragma("unroll")                                                \
                    for (int l = 0; l < LL; ++l)                                     \
                        if ((GB) & (1u << l)) gmax[l] = fmaxf(gmax[l], XV);          \
                    if ((YV) > 0.0f) gtb |= (GB);                                    \
                    if ((NV) > 0.0f) gnb |= (GB);                                    \
                }
            P1(g0, xv.x, yv.x, nvv.x)
            P1(g1, xv.y, yv.y, nvv.y)
            P1(g2, xv.z, yv.z, nvv.z)
            P1(g3, xv.w, yv.w, nvv.w)
            #undef P1
        }
    }

    // ---- warp-reduce aggregates ----
    #pragma unroll
    for (int off = 16; off > 0; off >>= 1) {
        #pragma unroll
        for (int l = 0; l < LL; ++l)
            gmax[l] = fmaxf(gmax[l], __shfl_xor_sync(fm, gmax[l], off));
        umax = fmaxf(umax, __shfl_xor_sync(fm, umax, off));
        gtb |= __shfl_xor_sync(fm, gtb, off);
        gnb |= __shfl_xor_sync(fm, gnb, off);
    }
    if (lane == 0) {
        #pragma unroll
        for (int l = 0; l < LL; ++l) s_gmax[w][l] = gmax[l];
        s_umax[w] = umax;
        s_gtb[w] = gtb;
        s_gnb[w] = gnb;
    }
    __syncthreads();

    const int total = s_ncand;                   // true count of x > TVAL

    // ---- top-16 selection ----
    float tk[TOPK];
    #pragma unroll
    for (int k = 0; k < TOPK; ++k) tk[k] = NI;

    #define INS(XV)                                                            \
        if ((XV) > tk[TOPK - 1]) {                                             \
            float _v = (XV);                                                   \
            _Pragma("unroll")                                                  \
            for (int k = 0; k < TOPK; ++k)                                     \
                if (_v > tk[k]) { float _tmp = tk[k]; tk[k] = _v; _v = _tmp; } \
        }

    if (total >= TOPK && total <= CAP) {
        // fast path: exact — all values > TVAL are in s_cand and 16th-largest > TVAL
        for (int i = t; i < total; i += NT) {
            float xv = s_cand[i];
            INS(xv)
        }
    } else {
        // rare exact fallback: full re-scan with unconditional insertion
        for (int i = t; i < CC; i += NT) {
            float xv = __ldg(xr + i);
            INS(xv)
        }
    }
    #undef INS

    #pragma unroll
    for (int k = 0; k < TOPK; ++k) s_top[t * TOPK + k] = tk[k];
    __syncthreads();

    // merge tree over NT top-16 lists
    for (int s = NT / 2; s >= 1; s >>= 1) {
        if (t < s) {
            float o[TOPK];
            const float* A  = &s_top[t * TOPK];
            const float* Bp = &s_top[(t + s) * TOPK];
            int i = 0, j = 0;
            #pragma unroll
            for (int k = 0; k < TOPK; ++k) {
                float avv = A[i], cv = Bp[j];
                if (avv >= cv) { o[k] = avv; ++i; } else { o[k] = cv; ++j; }
            }
            float* Aw = &s_top[t * TOPK];
            #pragma unroll
            for (int k = 0; k < TOPK; ++k) Aw[k] = o[k];
        }
        __syncthreads();
    }

    // ---- per-row loss (thread 0) ----
    if (t == 0) {
        float gmaxA[LL];
        #pragma unroll
        for (int l = 0; l < LL; ++l) gmaxA[l] = NI;
        float umaxA = NI;
        unsigned int gtA = 0, gnA = 0;
        for (int wv = 0; wv < NW; ++wv) {
            #pragma unroll
            for (int l = 0; l < LL; ++l) gmaxA[l] = fmaxf(gmaxA[l], s_gmax[wv][l]);
            umaxA = fmaxf(umaxA, s_umax[wv]);
            gtA |= s_gtb[wv];
            gnA |= s_gnb[wv];
        }

        float t16   = s_top[TOPK - 1];               // exact 16th-largest raw x
        float thres = fmaxf(sigm(t16), ALPHA_OTHER);

        float loss;
        if (gtA) {
            loss = 0.0f;
            #pragma unroll
            for (int l = 0; l < LL; ++l) {
                float gm = sigm(gmaxA[l]);
                loss += ((gtA >> l) & 1u) ? rankl(gm, thres)
                                          : rankl(thres, gm);
            }
        } else {
            float um = sigm(umaxA);
            float negs = 0.0f;                       // torch starts at 0
            if (gnA) {
                float nm = NI;
                #pragma unroll
                for (int l = 0; l < LL; ++l)
                    if ((gnA >> l) & 1u) nm = fmaxf(nm, gmaxA[l]);
                negs = sigm(nm);
            }
            loss = (1.0f - ALPHA) * rankl(thres, um) + ALPHA * rankl(thres, negs);
        }
        g_partial[b] = loss;
    }

    // ---- fused deterministic mean: last CTA reduces all partials ----
    if (t == 0) {
        __threadfence();
        int old = atomicAdd(&g_done, 1);
        s_last = (old == BB - 1);
    }
    __syncthreads();
    if (s_last) {
        float acc = 0.0f;
        for (int i = t; i < BB; i += NT) acc += g_partial[i];   // fixed order
        s_top[t] = acc;
        __syncthreads();
        for (int st = NT / 2; st > 0; st >>= 1) {
            if (t < st) s_top[t] += s_top[t + st];
            __syncthreads();
        }
        if (t == 0) { out[0] = s_top[0] / (float)BB; g_done = 0; }
    }
}

extern "C" void kernel_launch(void* const* d_in, const int* in_sizes, int n_in,
                              void* d_out, int out_size) {
    (void)in_sizes; (void)n_in; (void)out_size;
    const float*         x  = (const float*)d_in[0];
    const float*         y  = (const float*)d_in[1];
    const float*         yn = (const float*)d_in[2];
    const unsigned char* m  = (const unsigned char*)d_in[3];

    prep_kernel<<<1, 1024>>>(m);
    row_kernel<<<BB, NT>>>(x, y, yn, (float*)d_out);
}

// round 9
// speedup vs baseline: 1.3370x; 1.1470x over previous
#include <cuda_runtime.h>
#include <cuda_bf16.h>
#include <cstdint>

#define BB    2048
#define CC    9605
#define LL    8
#define NT    256
#define TOPK  16
#define TVAL  2.0f
#define CAP   1024
#define NW    (NT / 32)

#define ALPHA   0.5f
#define ALPHA1  0.05f
#define ALPHA2  2.0f
#define ALPHA3  5.0f
#define ALPHA_OTHER 0.3f

// Scratch (no cudaMalloc allowed)
__device__ float         g_partial[BB];
__device__ unsigned char g_gbits[CC + 16];
__device__ unsigned int  g_glist[CC];      // sorted grouped classes: idx | (gb<<16)
__device__ int           g_ng;             // number of grouped classes
__device__ int           g_done;           // zero-init; reset by last block each call

__device__ __forceinline__ float sigm(float v) { return 1.0f / (1.0f + __expf(-v)); }

__device__ __forceinline__ float rankl(float x1, float x2) {
    float d = x2 - x1 + ALPHA1;
    float s = 1.0f / (1.0f + __expf(-ALPHA3 * d));
    return d > 0.0f ? ALPHA2 * s : s;
}

// ---------------------------------------------------------------------------
// prep: ONE block of 1024.
// Phase A: classify mask dtype from byte pattern.
//   f32 1.0 -> bytes {00,00,80,3F}: some byte has a bit above bit0 -> word mode
//   i32 1   -> ones only at offset%4==0                            -> word mode
//   bool    -> 0x01 at arbitrary byte offsets                      -> byte mode
// Phase B: per-class membership byte.
// Phase C: stable compaction of grouped classes into g_glist (sorted by idx).
// ---------------------------------------------------------------------------
__global__ __launch_bounds__(1024) void prep_kernel(const unsigned char* __restrict__ mraw) {
    __shared__ int s_gt1, s_mis;
    __shared__ int s_wtot[32], s_wex[32];
    __shared__ int s_base, s_ctot;
    const int t = threadIdx.x, w = t >> 5, lane = t & 31;
    const unsigned fm = 0xFFFFFFFFu;

    if (t == 0) { s_gt1 = 0; s_mis = 0; s_base = 0; }
    __syncthreads();
    const unsigned int* mw = (const unsigned int*)mraw;
    unsigned int a = 0, bm = 0;
    for (int i = t; i < (CC * LL) / 4; i += 1024) {   // 19210 words exact
        unsigned int wv = mw[i];
        a  |= (wv & 0xFEFEFEFEu);   // any byte >= 2 anywhere
        bm |= (wv & 0x01010100u);   // bit0 set in bytes at offset%4 != 0
    }
    if (a)  atomicOr(&s_gt1, 1);
    if (bm) atomicOr(&s_mis, 1);
    __syncthreads();
    const int bytemode = (!s_gt1) && s_mis;

    for (int c = t; c < CC; c += 1024) {
        unsigned int bits = 0;
        if (bytemode) {
            #pragma unroll
            for (int l = 0; l < LL; ++l)
                if (mraw[l * CC + c] != 0) bits |= (1u << l);
        } else {
            #pragma unroll
            for (int l = 0; l < LL; ++l)
                if (mw[l * CC + c] != 0u) bits |= (1u << l);
        }
        g_gbits[c] = (unsigned char)bits;
    }
    __syncthreads();

    // Phase C: chunked stable compaction (ballot-scan within chunk of 1024)
    for (int base = 0; base < CC; base += 1024) {
        int c = base + t;
        unsigned int gb = (c < CC) ? (unsigned int)g_gbits[c] : 0u;
        int ind = (gb != 0u);
        unsigned int wm = __ballot_sync(fm, ind);
        int rank = __popc(wm & ((1u << lane) - 1u));
        if (lane == 0) s_wtot[w] = __popc(wm);
        __syncthreads();
        if (w == 0) {
            int v = s_wtot[lane];
            int inc = v;
            #pragma unroll
            for (int off = 1; off < 32; off <<= 1) {
                int u = __shfl_up_sync(fm, inc, off);
                if (lane >= off) inc += u;
            }
            s_wex[lane] = inc - v;                 // exclusive warp offsets
            if (lane == 31) s_ctot = inc;          // chunk total
        }
        __syncthreads();
        if (ind) g_glist[s_base + s_wex[w] + rank] = (unsigned int)c | (gb << 16);
        __syncthreads();
        if (t == 0) s_base += s_ctot;
        __syncthreads();
    }
    if (t == 0) g_ng = s_base;
}

// ---------------------------------------------------------------------------
// row_kernel: one CTA per sample.
// Loop 1: stream x (2 packs/iter), warp-aggregated top-16 candidate compaction.
// Loop 2: gather over the grouped-class list (dense group-max / gt / gn work;
//         x re-read hits L2, y/yn as semi-coalesced __ldcs gathers).
// Exact top-16 from candidates when 16 <= count <= CAP; else exact fallback.
// Last CTA reduces the 2048 partials deterministically.
// ---------------------------------------------------------------------------
__global__ __launch_bounds__(NT) void row_kernel(const float* __restrict__ x,
                                                 const float* __restrict__ y,
                                                 const float* __restrict__ yn,
                                                 float* __restrict__ out) {
    __shared__ float s_cand[CAP];
    __shared__ float s_top[NT * TOPK];          // merge workspace / final reduce buf
    __shared__ float s_gmax[NW][LL];
    __shared__ float s_umax[NW];
    __shared__ unsigned int s_gtb[NW], s_gnb[NW];
    __shared__ int s_ncand, s_last;

    const int b = blockIdx.x, t = threadIdx.x, w = t >> 5, lane = t & 31;
    const size_t base = (size_t)b * CC;
    const float* __restrict__ xr = x + base;
    const float* __restrict__ yr = y + base;
    const float* __restrict__ nr = yn + base;

    // alignment: (b*9605) % 4 == b % 4  (9605 % 4 == 1)
    const int av = b & 3;
    const int p  = (4 - av) & 3;             // scalar peel count
    const int nv = (CC - p) >> 2;            // float4 count
    const int r  = (CC - p) & 3;             // scalar tail count

    if (t == 0) s_ncand = 0;
    __syncthreads();

    const float NI = __int_as_float(0xff800000);
    const unsigned fm = 0xFFFFFFFFu;

    // ---- peel + tail candidates (<= 5 elements; all threads reach ballot) ----
    {
        int active = (t < p + r);
        float xv = NI;
        if (active) {
            int idx = (t < p) ? t : (p + 4 * nv + (t - p));
            xv = __ldg(xr + idx);
        }
        unsigned int mk = __ballot_sync(fm, active && xv > TVAL);
        if (mk && w == 0) {                      // peel elements live in warp 0 only
            int bpos = 0;
            if (lane == 0) bpos = atomicAdd(&s_ncand, __popc(mk));
            bpos = __shfl_sync(fm, bpos, 0);
            if (active && xv > TVAL) {
                int my = bpos + __popc(mk & ((1u << lane) - 1u));
                if (my < CAP) s_cand[my] = xv;
            }
        }
    }

    // ---- Loop 1: stream x, 2 packs/iter, uniform trip count (ballot-safe) ----
    const float4* __restrict__ x4 = (const float4*)(xr + p);

    for (int v0 = 0; v0 < nv; v0 += 2 * NT) {
        const int va = v0 + t, vb = v0 + NT + t;
        float4 xa, xb;
        if (va < nv) xa = __ldg(x4 + va); else { xa.x = NI; xa.y = NI; xa.z = NI; xa.w = NI; }
        if (vb < nv) xb = __ldg(x4 + vb); else { xb.x = NI; xb.y = NI; xb.z = NI; xb.w = NI; }

        #define CBLK(XV)                                                           \
        {                                                                          \
            unsigned int m0 = __ballot_sync(fm, (XV).x > TVAL);                    \
            unsigned int m1 = __ballot_sync(fm, (XV).y > TVAL);                    \
            unsigned int m2 = __ballot_sync(fm, (XV).z > TVAL);                    \
            unsigned int m3 = __ballot_sync(fm, (XV).w > TVAL);                    \
            if (m0 | m1 | m2 | m3) {                                               \
                int n = __popc(m0) + __popc(m1) + __popc(m2) + __popc(m3);         \
                int bpos = 0;                                                      \
                if (lane == 0) bpos = atomicAdd(&s_ncand, n);                      \
                bpos = __shfl_sync(fm, bpos, 0);                                   \
                unsigned int lt = (1u << lane) - 1u;                               \
                int o = bpos;                                                      \
                if ((XV).x > TVAL) { int my = o + __popc(m0 & lt); if (my < CAP) s_cand[my] = (XV).x; } \
                o += __popc(m0);                                                   \
                if ((XV).y > TVAL) { int my = o + __popc(m1 & lt); if (my < CAP) s_cand[my] = (XV).y; } \
                o += __popc(m1);                                                   \
                if ((XV).z > TVAL) { int my = o + __popc(m2 & lt); if (my < CAP) s_cand[my] = (XV).z; } \
                o += __popc(m2);                                                   \
                if ((XV).w > TVAL) { int my = o + __popc(m3 & lt); if (my < CAP) s_cand[my] = (XV).w; } \
            }                                                                      \
        }
        CBLK(xa)
        CBLK(xb)
        #undef CBLK
    }

    // ---- Loop 2: dense gather over grouped classes (no collectives: ragged OK) ----
    float gmax[LL];
    #pragma unroll
    for (int l = 0; l < LL; ++l) gmax[l] = NI;
    float umax = NI;
    unsigned int gtb = 0, gnb = 0;
    const int ng = g_ng;

    for (int i0 = 0; i0 < ng; i0 += 2 * NT) {
        const int ia = i0 + t, ib = i0 + NT + t;
        unsigned int e1 = 0, e2 = 0;
        if (ia < ng) e1 = __ldg(&g_glist[ia]);
        if (ib < ng) e2 = __ldg(&g_glist[ib]);

        #define GBLK(E)                                                            \
        if (E) {                                                                   \
            int c = (E) & 0xFFFFu;                                                 \
            unsigned int gb = (E) >> 16;                                           \
            float xv  = __ldg(xr + c);            /* L2-hot from loop 1 */         \
            float yv  = __ldcs(yr + c);                                            \
            float nvv = __ldcs(nr + c);                                            \
            umax = fmaxf(umax, xv);                                                \
            _Pragma("unroll")                                                      \
            for (int l = 0; l < LL; ++l)                                           \
                if (gb & (1u << l)) gmax[l] = fmaxf(gmax[l], xv);                  \
            if (yv  > 0.0f) gtb |= gb;                                             \
            if (nvv > 0.0f) gnb |= gb;                                             \
        }
        GBLK(e1)
        GBLK(e2)
        #undef GBLK
    }

    // ---- warp-reduce aggregates (full reconvergence before shuffles) ----
    #pragma unroll
    for (int off = 16; off > 0; off >>= 1) {
        #pragma unroll
        for (int l = 0; l < LL; ++l)
            gmax[l] = fmaxf(gmax[l], __shfl_xor_sync(fm, gmax[l], off));
        umax = fmaxf(umax, __shfl_xor_sync(fm, umax, off));
        gtb |= __shfl_xor_sync(fm, gtb, off);
        gnb |= __shfl_xor_sync(fm, gnb, off);
    }
    if (lane == 0) {
        #pragma unroll
        for (int l = 0; l < LL; ++l) s_gmax[w][l] = gmax[l];
        s_umax[w] = umax;
        s_gtb[w] = gtb;
        s_gnb[w] = gnb;
    }
    __syncthreads();

    const int total = s_ncand;                   // true count of x > TVAL

    // ---- top-16 selection ----
    float tk[TOPK];
    #pragma unroll
    for (int k = 0; k < TOPK; ++k) tk[k] = NI;

    #define INS(XV)                                                            \
        if ((XV) > tk[TOPK - 1]) {                                             \
            float _v = (XV);                                                   \
            _Pragma("unroll")                                                  \
            for (int k = 0; k < TOPK; ++k)                                     \
                if (_v > tk[k]) { float _tmp = tk[k]; tk[k] = _v; _v = _tmp; } \
        }

    if (total >= TOPK && total <= CAP) {
        // fast path: exact — all values > TVAL are in s_cand and 16th-largest > TVAL
        for (int i = t; i < total; i += NT) {
            float xv = s_cand[i];
            INS(xv)
        }
    } else {
        // rare exact fallback: full re-scan with unconditional insertion
        for (int i = t; i < CC; i += NT) {
            float xv = __ldg(xr + i);
            INS(xv)
        }
    }
    #undef INS

    #pragma unroll
    for (int k = 0; k < TOPK; ++k) s_top[t * TOPK + k] = tk[k];
    __syncthreads();

    // merge tree over NT top-16 lists
    for (int s = NT / 2; s >= 1; s >>= 1) {
        if (t < s) {
            float o[TOPK];
            const float* A  = &s_top[t * TOPK];
            const float* Bp = &s_top[(t + s) * TOPK];
            int i = 0, j = 0;
            #pragma unroll
            for (int k = 0; k < TOPK; ++k) {
                float avv = A[i], cv = Bp[j];
                if (avv >= cv) { o[k] = avv; ++i; } else { o[k] = cv; ++j; }
            }
            float* Aw = &s_top[t * TOPK];
            #pragma unroll
            for (int k = 0; k < TOPK; ++k) Aw[k] = o[k];
        }
        __syncthreads();
    }

    // ---- per-row loss (thread 0) ----
    if (t == 0) {
        float gmaxA[LL];
        #pragma unroll
        for (int l = 0; l < LL; ++l) gmaxA[l] = NI;
        float umaxA = NI;
        unsigned int gtA = 0, gnA = 0;
        for (int wv = 0; wv < NW; ++wv) {
            #pragma unroll
            for (int l = 0; l < LL; ++l) gmaxA[l] = fmaxf(gmaxA[l], s_gmax[wv][l]);
            umaxA = fmaxf(umaxA, s_umax[wv]);
            gtA |= s_gtb[wv];
            gnA |= s_gnb[wv];
        }

        float t16   = s_top[TOPK - 1];               // exact 16th-largest raw x
        float thres = fmaxf(sigm(t16), ALPHA_OTHER);

        float loss;
        if (gtA) {
            loss = 0.0f;
            #pragma unroll
            for (int l = 0; l < LL; ++l) {
                float gm = sigm(gmaxA[l]);
                loss += ((gtA >> l) & 1u) ? rankl(gm, thres)
                                          : rankl(thres, gm);
            }
        } else {
            float um = sigm(umaxA);
            float negs = 0.0f;                       // torch starts at 0
            if (gnA) {
                float nm = NI;
                #pragma unroll
                for (int l = 0; l < LL; ++l)
                    if ((gnA >> l) & 1u) nm = fmaxf(nm, gmaxA[l]);
                negs = sigm(nm);
            }
            loss = (1.0f - ALPHA) * rankl(thres, um) + ALPHA * rankl(thres, negs);
        }
        g_partial[b] = loss;
    }

    // ---- fused deterministic mean: last CTA reduces all partials ----
    if (t == 0) {
        __threadfence();
        int old = atomicAdd(&g_done, 1);
        s_last = (old == BB - 1);
    }
    __syncthreads();
    if (s_last) {
        float acc = 0.0f;
        for (int i = t; i < BB; i += NT) acc += g_partial[i];   // fixed order
        s_top[t] = acc;
        __syncthreads();
        for (int st = NT / 2; st > 0; st >>= 1) {
            if (t < st) s_top[t] += s_top[t + st];
            __syncthreads();
        }
        if (t == 0) { out[0] = s_top[0] / (float)BB; g_done = 0; }
    }
}

extern "C" void kernel_launch(void* const* d_in, const int* in_sizes, int n_in,
                              void* d_out, int out_size) {
    (void)in_sizes; (void)n_in; (void)out_size;
    const float*         x  = (const float*)d_in[0];
    const float*         y  = (const float*)d_in[1];
    const float*         yn = (const float*)d_in[2];
    const unsigned char* m  = (const unsigned char*)d_in[3];

    prep_kernel<<<1, 1024>>>(m);
    row_kernel<<<BB, NT>>>(x, y, yn, (float*)d_out);
}

// round 10
// speedup vs baseline: 1.6837x; 1.2593x over previous
#include <cuda_runtime.h>
#include <cuda_bf16.h>
#include <cstdint>

#define BB    2048
#define CC    9605
#define LL    8
#define NT    256
#define TOPK  16
#define TVAL  2.0f
#define CAP   1024
#define NW    (NT / 32)

#define ALPHA   0.5f
#define ALPHA1  0.05f
#define ALPHA2  2.0f
#define ALPHA3  5.0f
#define ALPHA_OTHER 0.3f

// Scratch (no cudaMalloc allowed)
__device__ float         g_partial[BB];
__device__ unsigned char g_gbits[CC + 16];
__device__ unsigned int  g_glist[CC];      // sorted grouped classes: idx | (gb<<16)
__device__ int           g_ng;             // number of grouped classes
__device__ int           g_fA, g_fB;       // mask-dtype flags (atomicOr; idempotent per fixed input)
__device__ int           g_done;           // zero-init; reset by last block each call

__device__ __forceinline__ float sigm(float v) { return 1.0f / (1.0f + __expf(-v)); }

__device__ __forceinline__ float rankl(float x1, float x2) {
    float d = x2 - x1 + ALPHA1;
    float s = 1.0f / (1.0f + __expf(-ALPHA3 * d));
    return d > 0.0f ? ALPHA2 * s : s;
}

// ---------------------------------------------------------------------------
// prep_a (multi-block): classify mask dtype from byte pattern.
//   f32 1.0 -> bytes {00,00,80,3F}: some byte has a bit above bit0 -> word mode
//   i32 1   -> ones only at offset%4==0                            -> word mode
//   bool    -> 0x01 at arbitrary byte offsets                      -> byte mode
// Flags accumulate via atomicOr; input is identical every call -> idempotent.
// ---------------------------------------------------------------------------
__global__ void prep_a_kernel(const unsigned char* __restrict__ mraw) {
    const unsigned int* mw = (const unsigned int*)mraw;
    unsigned int a = 0, bm = 0;
    int i = blockIdx.x * blockDim.x + threadIdx.x;
    const int n = (CC * LL) / 4;                 // 19210 words exact
    for (; i < n; i += gridDim.x * blockDim.x) {
        unsigned int wv = __ldg(mw + i);
        a  |= (wv & 0xFEFEFEFEu);   // any byte >= 2 anywhere
        bm |= (wv & 0x01010100u);   // bit0 set in bytes at offset%4 != 0
    }
    if (a)  atomicOr(&g_fA, 1);
    if (bm) atomicOr(&g_fB, 1);
}

// ---------------------------------------------------------------------------
// prep_b (multi-block): per-class membership byte.
// ---------------------------------------------------------------------------
__global__ void prep_b_kernel(const unsigned char* __restrict__ mraw) {
    const int bytemode = (!g_fA) && g_fB;
    const unsigned int* mw = (const unsigned int*)mraw;
    int c = blockIdx.x * blockDim.x + threadIdx.x;
    if (c >= CC) return;
    unsigned int bits = 0;
    if (bytemode) {
        #pragma unroll
        for (int l = 0; l < LL; ++l)
            if (mraw[l * CC + c] != 0) bits |= (1u << l);
    } else {
        #pragma unroll
        for (int l = 0; l < LL; ++l)
            if (mw[l * CC + c] != 0u) bits |= (1u << l);
    }
    g_gbits[c] = (unsigned char)bits;
}

// ---------------------------------------------------------------------------
// prep_c (ONE block): stable compaction of grouped classes into g_glist.
// ---------------------------------------------------------------------------
__global__ __launch_bounds__(1024) void prep_c_kernel() {
    __shared__ int s_wtot[32], s_wex[32];
    __shared__ int s_base, s_ctot;
    const int t = threadIdx.x, w = t >> 5, lane = t & 31;
    const unsigned fm = 0xFFFFFFFFu;
    if (t == 0) s_base = 0;
    __syncthreads();

    for (int base = 0; base < CC; base += 1024) {
        int c = base + t;
        unsigned int gb = (c < CC) ? (unsigned int)g_gbits[c] : 0u;
        int ind = (gb != 0u);
        unsigned int wm = __ballot_sync(fm, ind);
        int rank = __popc(wm & ((1u << lane) - 1u));
        if (lane == 0) s_wtot[w] = __popc(wm);
        __syncthreads();
        if (w == 0) {
            int v = s_wtot[lane];
            int inc = v;
            #pragma unroll
            for (int off = 1; off < 32; off <<= 1) {
                int u = __shfl_up_sync(fm, inc, off);
                if (lane >= off) inc += u;
            }
            s_wex[lane] = inc - v;                 // exclusive warp offsets
            if (lane == 31) s_ctot = inc;          // chunk total
        }
        __syncthreads();
        if (ind) g_glist[s_base + s_wex[w] + rank] = (unsigned int)c | (gb << 16);
        __syncthreads();
        if (t == 0) s_base += s_ctot;
        __syncthreads();
    }
    if (t == 0) g_ng = s_base;
}

// ---------------------------------------------------------------------------
// row_kernel: one CTA per sample.
// Loop 1: stream x/y/yn fully coalesced (2 packs/iter). Top-16 candidate
//   compaction on x via warp-aggregated ballots; y/yn positives detected via
//   one ballot per pack (rare -> warp-uniform gated gbit lookup). NO gathers
//   of y/yn anywhere.
// Loop 2: x-only gather over grouped-class list (L2-hot) for group maxes.
// Selection: barrier-free rank-count over candidates (exact, deterministic).
// Last CTA reduces the 2048 partials deterministically.
// ---------------------------------------------------------------------------
__global__ __launch_bounds__(NT) void row_kernel(const float* __restrict__ x,
                                                 const float* __restrict__ y,
                                                 const float* __restrict__ yn,
                                                 float* __restrict__ out) {
    __shared__ float s_cand[CAP];
    __shared__ float s_red[NT];
    __shared__ float s_gmax[NW][LL];
    __shared__ float s_umax[NW];
    __shared__ unsigned int s_gtb[NW], s_gnb[NW];
    __shared__ float s_t16;
    __shared__ int s_ncand, s_last;

    const int b = blockIdx.x, t = threadIdx.x, w = t >> 5, lane = t & 31;
    const size_t base = (size_t)b * CC;
    const float* __restrict__ xr = x + base;
    const float* __restrict__ yr = y + base;
    const float* __restrict__ nr = yn + base;

    // alignment: (b*9605) % 4 == b % 4  (9605 % 4 == 1)
    const int av = b & 3;
    const int p  = (4 - av) & 3;             // scalar peel count
    const int nv = (CC - p) >> 2;            // float4 count
    const int r  = (CC - p) & 3;             // scalar tail count

    if (t == 0) s_ncand = 0;
    __syncthreads();

    const float NI = __int_as_float(0xff800000);
    const unsigned fm = 0xFFFFFFFFu;
    unsigned int gtb = 0, gnb = 0;

    // ---- peel + tail (<= 5 elements; all threads reach the ballot) ----
    {
        int active = (t < p + r);
        int idx = 0;
        float xv = NI;
        if (active) {
            idx = (t < p) ? t : (p + 4 * nv + (t - p));
            xv = __ldg(xr + idx);
        }
        unsigned int mk = __ballot_sync(fm, active && xv > TVAL);
        if (mk && w == 0) {                      // peel elements live in warp 0 only
            int bpos = 0;
            if (lane == 0) bpos = atomicAdd(&s_ncand, __popc(mk));
            bpos = __shfl_sync(fm, bpos, 0);
            if (active && xv > TVAL) {
                int my = bpos + __popc(mk & ((1u << lane) - 1u));
                if (my < CAP) s_cand[my] = xv;
            }
        }
        if (active) {
            unsigned int gb = g_gbits[idx];
            if (gb) {
                if (__ldg(yr + idx) > 0.0f) gtb |= gb;
                if (__ldg(nr + idx) > 0.0f) gnb |= gb;
            }
        }
    }

    // ---- Loop 1: coalesced stream of x/y/yn, 2 packs/iter, uniform trips ----
    const float4* __restrict__ x4 = (const float4*)(xr + p);
    const float4* __restrict__ y4 = (const float4*)(yr + p);
    const float4* __restrict__ n4 = (const float4*)(nr + p);

    for (int v0 = 0; v0 < nv; v0 += 2 * NT) {
        const int va = v0 + t, vb = v0 + NT + t;
        const bool ia = (va < nv), ib = (vb < nv);
        float4 xa, xb, ya, yb, na, nb;
        if (ia) { xa = __ldg(x4 + va); ya = __ldcs(y4 + va); na = __ldcs(n4 + va); }
        else    { xa.x=NI;xa.y=NI;xa.z=NI;xa.w=NI; ya.x=0;ya.y=0;ya.z=0;ya.w=0; na=ya; }
        if (ib) { xb = __ldg(x4 + vb); yb = __ldcs(y4 + vb); nb = __ldcs(n4 + vb); }
        else    { xb.x=NI;xb.y=NI;xb.z=NI;xb.w=NI; yb.x=0;yb.y=0;yb.z=0;yb.w=0; nb=yb; }

        // candidate compaction on x (warp-aggregated, ballot-uniform)
        #define CBLK(XV)                                                           \
        {                                                                          \
            unsigned int m0 = __ballot_sync(fm, (XV).x > TVAL);                    \
            unsigned int m1 = __ballot_sync(fm, (XV).y > TVAL);                    \
            unsigned int m2 = __ballot_sync(fm, (XV).z > TVAL);                    \
            unsigned int m3 = __ballot_sync(fm, (XV).w > TVAL);                    \
            if (m0 | m1 | m2 | m3) {                                               \
                int n = __popc(m0) + __popc(m1) + __popc(m2) + __popc(m3);         \
                int bpos = 0;                                                      \
                if (lane == 0) bpos = atomicAdd(&s_ncand, n);                      \
                bpos = __shfl_sync(fm, bpos, 0);                                   \
                unsigned int lt = (1u << lane) - 1u;                               \
                int o = bpos;                                                      \
                if ((XV).x > TVAL) { int my = o + __popc(m0 & lt); if (my < CAP) s_cand[my] = (XV).x; } \
                o += __popc(m0);                                                   \
                if ((XV).y > TVAL) { int my = o + __popc(m1 & lt); if (my < CAP) s_cand[my] = (XV).y; } \
                o += __popc(m1);                                                   \
                if ((XV).z > TVAL) { int my = o + __popc(m2 & lt); if (my < CAP) s_cand[my] = (XV).z; } \
                o += __popc(m2);                                                   \
                if ((XV).w > TVAL) { int my = o + __popc(m3 & lt); if (my < CAP) s_cand[my] = (XV).w; } \
            }                                                                      \
        }
        CBLK(xa)
        CBLK(xb)
        #undef CBLK

        // rare positive detection on streamed y / yn (one ballot per pack)
        #define PBLK(YV, VI, DST)                                                  \
        {                                                                          \
            bool _hit = ((YV).x > 0.0f) | ((YV).y > 0.0f) |                        \
                        ((YV).z > 0.0f) | ((YV).w > 0.0f);                         \
            unsigned int _m = __ballot_sync(fm, _hit);                             \
            if (_m) {                          /* warp-uniform, almost never */    \
                if (_hit) {                                                        \
                    int ci = p + 4 * (VI);                                         \
                    if ((YV).x > 0.0f) DST |= (unsigned int)g_gbits[ci];           \
                    if ((YV).y > 0.0f) DST |= (unsigned int)g_gbits[ci + 1];       \
                    if ((YV).z > 0.0f) DST |= (unsigned int)g_gbits[ci + 2];       \
                    if ((YV).w > 0.0f) DST |= (unsigned int)g_gbits[ci + 3];       \
                }                                                                  \
            }                                                                      \
        }
        PBLK(ya, va, gtb)
        PBLK(yb, vb, gtb)
        PBLK(na, va, gnb)
        PBLK(nb, vb, gnb)
        #undef PBLK
    }

    // ---- Loop 2: x-only gather over grouped classes (L2-hot; no collectives) ----
    float gmax[LL];
    #pragma unroll
    for (int l = 0; l < LL; ++l) gmax[l] = NI;
    float umax = NI;
    const int ng = g_ng;

    for (int i0 = 0; i0 < ng; i0 += 2 * NT) {
        const int ia = i0 + t, ib = i0 + NT + t;
        unsigned int e1 = 0, e2 = 0;
        if (ia < ng) e1 = __ldg(&g_glist[ia]);
        if (ib < ng) e2 = __ldg(&g_glist[ib]);

        #define GBLK(E)                                                            \
        if (E) {                                                                   \
            int c = (E) & 0xFFFFu;                                                 \
            unsigned int gb = (E) >> 16;                                           \
            float xv = __ldg(xr + c);             /* L2-hot from loop 1 */         \
            umax = fmaxf(umax, xv);                                                \
            _Pragma("unroll")                                                      \
            for (int l = 0; l < LL; ++l)                                           \
                if (gb & (1u << l)) gmax[l] = fmaxf(gmax[l], xv);                  \
        }
        GBLK(e1)
        GBLK(e2)
        #undef GBLK
    }

    // ---- warp-reduce aggregates ----
    #pragma unroll
    for (int off = 16; off > 0; off >>= 1) {
        #pragma unroll
        for (int l = 0; l < LL; ++l)
            gmax[l] = fmaxf(gmax[l], __shfl_xor_sync(fm, gmax[l], off));
        umax = fmaxf(umax, __shfl_xor_sync(fm, umax, off));
        gtb |= __shfl_xor_sync(fm, gtb, off);
        gnb |= __shfl_xor_sync(fm, gnb, off);
    }
    if (lane == 0) {
        #pragma unroll
        for (int l = 0; l < LL; ++l) s_gmax[w][l] = gmax[l];
        s_umax[w] = umax;
        s_gtb[w] = gtb;
        s_gnb[w] = gnb;
    }
    __syncthreads();

    int nc = s_ncand;                            // true count of x > TVAL

    // ---- exact fallback (essentially never): rebuild s_cand from full row ----
    if (nc < TOPK || nc > CAP) {
        __syncthreads();                         // everyone done reading s_ncand
        if (t < 64) {
            float tk[TOPK];
            #pragma unroll
            for (int k = 0; k < TOPK; ++k) tk[k] = NI;
            for (int i = t; i < CC; i += 64) {
                float xv = __ldg(xr + i);
                if (xv > tk[TOPK - 1]) {
                    float _v = xv;
                    #pragma unroll
                    for (int k = 0; k < TOPK; ++k)
                        if (_v > tk[k]) { float _tmp = tk[k]; tk[k] = _v; _v = _tmp; }
                }
            }
            #pragma unroll
            for (int k = 0; k < TOPK; ++k) s_cand[t * TOPK + k] = tk[k];
        }
        __syncthreads();
        nc = 64 * TOPK;                          // top-16 of row is within these 1024
    }

    // ---- rank-count selection: 16th-largest = v with #{>v} <= 15 < #{>=v} ----
    for (int i = t; i < nc; i += NT) {
        float v = s_cand[i];
        int cg = 0, ce = 0;
        for (int j = 0; j < nc; ++j) {
            float u = s_cand[j];                 // broadcast read, conflict-free
            cg += (u > v);
            ce += (u == v);
        }
        if (cg <= TOPK - 1 && cg + ce >= TOPK) s_t16 = v;   // unique value; benign race
    }
    __syncthreads();

    // ---- per-row loss (thread 0) ----
    if (t == 0) {
        float gmaxA[LL];
        #pragma unroll
        for (int l = 0; l < LL; ++l) gmaxA[l] = NI;
        float umaxA = NI;
        unsigned int gtA = 0, gnA = 0;
        for (int wv = 0; wv < NW; ++wv) {
            #pragma unroll
            for (int l = 0; l < LL; ++l) gmaxA[l] = fmaxf(gmaxA[l], s_gmax[wv][l]);
            umaxA = fmaxf(umaxA, s_umax[wv]);
            gtA |= s_gtb[wv];
            gnA |= s_gnb[wv];
        }

        float thres = fmaxf(sigm(s_t16), ALPHA_OTHER);

        float loss;
        if (gtA) {
            loss = 0.0f;
            #pragma unroll
            for (int l = 0; l < LL; ++l) {
                float gm = sigm(gmaxA[l]);
                loss += ((gtA >> l) & 1u) ? rankl(gm, thres)
                                          : rankl(thres, gm);
            }
        } else {
            float um = sigm(umaxA);
            float negs = 0.0f;                   // torch starts at 0
            if (gnA) {
                float nm = NI;
                #pragma unroll
                for (int l = 0; l < LL; ++l)
                    if ((gnA >> l) & 1u) nm = fmaxf(nm, gmaxA[l]);
                negs = sigm(nm);
            }
            loss = (1.0f - ALPHA) * rankl(thres, um) + ALPHA * rankl(thres, negs);
        }
        g_partial[b] = loss;
    }

    // ---- fused deterministic mean: last CTA reduces all partials ----
    if (t == 0) {
        __threadfence();
        int old = atomicAdd(&g_done, 1);
        s_last = (old == BB - 1);
    }
    __syncthreads();
    if (s_last) {
        float acc = 0.0f;
        for (int i = t; i < BB; i += NT) acc += g_partial[i];   // fixed order
        s_red[t] = acc;
        __syncthreads();
        for (int st = NT / 2; st > 0; st >>= 1) {
            if (t < st) s_red[t] += s_red[t + st];
            __syncthreads();
        }
        if (t == 0) { out[0] = s_red[0] / (float)BB; g_done = 0; }
    }
}

extern "C" void kernel_launch(void* const* d_in, const int* in_sizes, int n_in,
                              void* d_out, int out_size) {
    (void)in_sizes; (void)n_in; (void)out_size;
    const float*         x  = (const float*)d_in[0];
    const float*         y  = (const float*)d_in[1];
    const float*         yn = (const float*)d_in[2];
    const unsigned char* m  = (const unsigned char*)d_in[3];

    prep_a_kernel<<<4, 1024>>>(m);
    prep_b_kernel<<<(CC + 1023) / 1024, 1024>>>(m);
    prep_c_kernel<<<1, 1024>>>();
    row_kernel<<<BB, NT>>>(x, y, yn, (float*)d_out);
}